// round 8
// baseline (speedup 1.0000x reference)
#include <cuda_runtime.h>
#include <cuda_bf16.h>

#define B_ 128
#define T_ 512
#define E_ 256
#define U_ 256

// U split: 176 columns in registers (88 u64), 80 columns in smem (40 u64)
#define UREG 176
#define USMEM 80
#define USTRIDE 84   // floats; 4*odd -> no extra LDS bank phases, 16B-aligned rows

typedef unsigned long long u64t;

// 64MB scratch: xw[t][b][u]
__device__ __align__(16) float g_xw[T_ * B_ * U_];

__device__ __forceinline__ u64t ffma2(u64t a, u64t b, u64t c) {
    u64t d;
    asm("fma.rn.f32x2 %0, %1, %2, %3;" : "=l"(d) : "l"(a), "l"(b), "l"(c));
    return d;
}
__device__ __forceinline__ u64t addx2(u64t a, u64t b) {
    u64t d;
    asm("add.rn.f32x2 %0, %1, %2;" : "=l"(d) : "l"(a), "l"(b));
    return d;
}
__device__ __forceinline__ float f2lo(u64t v) { return __uint_as_float((unsigned)(v & 0xffffffffull)); }
__device__ __forceinline__ float f2hi(u64t v) { return __uint_as_float((unsigned)(v >> 32)); }
__device__ __forceinline__ float tanh_fast(float x) {
    float ex = __expf(2.0f * x);
    return 1.0f - __fdividef(2.0f, ex + 1.0f);
}

// ---------------------------------------------------------------------------
// Phase 1: xw[t][b][u] = sum_e emb[sentence[b][t]][e] * W[u][e]  (unchanged)
// ---------------------------------------------------------------------------
__global__ void __launch_bounds__(256)
xw_kernel(const int* __restrict__ sent, const float* __restrict__ emb,
          const float* __restrict__ Wm)
{
    __shared__ __align__(16) float2 As2[16 * 64];
    __shared__ __align__(16) float  Bs[16 * 256];
    __shared__ int idx[64];

    const int tid = threadIdx.x;
    const int r0 = blockIdx.x * 64;
    const int t  = r0 >> 7;
    const int b0 = r0 & 127;

    if (tid < 64) idx[tid] = sent[(b0 + tid) * T_ + t];
    __syncthreads();

    const int tx = tid & 15;
    const int ty = tid >> 4;
    const int arow = tid >> 2;
    const int aq = tid & 3;

    u64t acc[4][8];
    #pragma unroll
    for (int i = 0; i < 4; i++)
        #pragma unroll
        for (int p = 0; p < 8; p++) acc[i][p] = 0ull;

    float4 va = *(const float4*)(emb + (size_t)idx[arow] * E_ + aq * 4);
    float4 vb0 = *(const float4*)(Wm + (size_t)tid * E_ + 0);
    float4 vb1 = *(const float4*)(Wm + (size_t)tid * E_ + 4);
    float4 vb2 = *(const float4*)(Wm + (size_t)tid * E_ + 8);
    float4 vb3 = *(const float4*)(Wm + (size_t)tid * E_ + 12);

    for (int ko = 0; ko < 16; ko++) {
        if (ko > 0) __syncthreads();

        As2[(aq * 4 + 0) * 64 + arow] = make_float2(va.x, va.x);
        As2[(aq * 4 + 1) * 64 + arow] = make_float2(va.y, va.y);
        As2[(aq * 4 + 2) * 64 + arow] = make_float2(va.z, va.z);
        As2[(aq * 4 + 3) * 64 + arow] = make_float2(va.w, va.w);
        {
            const float v[16] = {vb0.x, vb0.y, vb0.z, vb0.w, vb1.x, vb1.y, vb1.z, vb1.w,
                                 vb2.x, vb2.y, vb2.z, vb2.w, vb3.x, vb3.y, vb3.z, vb3.w};
            #pragma unroll
            for (int j = 0; j < 16; j++) Bs[j * 256 + tid] = v[j];
        }
        __syncthreads();

        if (ko < 15) {
            const int kb = (ko + 1) * 16;
            va  = *(const float4*)(emb + (size_t)idx[arow] * E_ + kb + aq * 4);
            vb0 = *(const float4*)(Wm + (size_t)tid * E_ + kb + 0);
            vb1 = *(const float4*)(Wm + (size_t)tid * E_ + kb + 4);
            vb2 = *(const float4*)(Wm + (size_t)tid * E_ + kb + 8);
            vb3 = *(const float4*)(Wm + (size_t)tid * E_ + kb + 12);
        }

        #pragma unroll
        for (int k = 0; k < 16; k++) {
            u64t ap[4];
            #pragma unroll
            for (int i = 0; i < 4; i++)
                ap[i] = *(const u64t*)&As2[k * 64 + ty * 4 + i];
            #pragma unroll
            for (int q = 0; q < 4; q++) {
                const ulonglong2 bq = *(const ulonglong2*)&Bs[k * 256 + q * 64 + tx * 4];
                #pragma unroll
                for (int i = 0; i < 4; i++) {
                    acc[i][2 * q + 0] = ffma2(bq.x, ap[i], acc[i][2 * q + 0]);
                    acc[i][2 * q + 1] = ffma2(bq.y, ap[i], acc[i][2 * q + 1]);
                }
            }
        }
    }

    #pragma unroll
    for (int i = 0; i < 4; i++) {
        const int rg = r0 + ty * 4 + i;
        #pragma unroll
        for (int q = 0; q < 4; q++) {
            float4 o;
            o.x = f2lo(acc[i][2 * q + 0]); o.y = f2hi(acc[i][2 * q + 0]);
            o.z = f2lo(acc[i][2 * q + 1]); o.w = f2hi(acc[i][2 * q + 1]);
            __stcs((float4*)(g_xw + (size_t)rg * U_ + q * 64 + tx * 4), o);
        }
    }
}

// ---------------------------------------------------------------------------
// Phase 2: single-CTA recurrence. One CTA = one batch row; thread t owns
// u-row t with the FULL 256-wide dot in-thread: U[t, 0:176] in registers,
// U[t, 176:256] in smem (padded stride, conflict-free LDS.128). h is a
// 256-float smem vector read via broadcast LDS.128. Per step: no reduce,
// no cluster, ONE __syncthreads. Double-buffered h.
// ---------------------------------------------------------------------------
__global__ void __launch_bounds__(256, 1)
rnn_kernel(const float* __restrict__ Um,
           const float* __restrict__ W1, const float* __restrict__ b1v,
           const float* __restrict__ W2, const float* __restrict__ b2v,
           float* __restrict__ outp)
{
    extern __shared__ __align__(16) float Usm[];        // [256][USTRIDE]
    __shared__ __align__(16) float hbuf[2][256];
    __shared__ float hid[32];

    const int tid = threadIdx.x;
    const int b = blockIdx.x;

    // U[tid, 0:176] -> registers (88 u64)
    u64t Ur[UREG / 2];
    {
        const u64t* p = (const u64t*)(Um + (size_t)tid * U_);
        #pragma unroll
        for (int q = 0; q < UREG / 2; q++) Ur[q] = p[q];
    }
    // U[tid, 176:256] -> smem row tid
    {
        const float4* src = (const float4*)(Um + (size_t)tid * U_ + UREG);
        float4* dst = (float4*)(Usm + tid * USTRIDE);
        #pragma unroll
        for (int k = 0; k < USMEM / 4; k++) dst[k] = src[k];
    }

    hbuf[0][tid] = 0.0f;
    hbuf[1][tid] = 0.0f;
    __syncthreads();

    float cxw = __ldcs(g_xw + (size_t)b * U_ + tid);

    for (int t = 0; t < T_; t++) {
        const int rb = t & 1;
        const int wb = rb ^ 1;

        // prefetch next step's xw (LDG latency spans the whole dot)
        const int tn = (t + 1 < T_) ? t + 1 : t;
        const float nxw = __ldcs(g_xw + (size_t)tn * (B_ * U_) + (size_t)b * U_ + tid);

        u64t a0 = 0ull, a1 = 0ull, a2 = 0ull, a3 = 0ull;

        const ulonglong2* hp2 = (const ulonglong2*)&hbuf[rb][0];   // 64 entries, broadcast
        // registers part: k = 0..43 covers j 0..175
        #pragma unroll
        for (int k = 0; k < UREG / 4; k++) {
            const ulonglong2 h = hp2[k];
            a0 = ffma2(Ur[2 * k + 0], h.x, a0);
            a1 = ffma2(Ur[2 * k + 1], h.y, a1);
        }
        // smem part: k = 44..63 covers j 176..255
        const ulonglong2* us2 = (const ulonglong2*)(Usm + tid * USTRIDE);
        #pragma unroll
        for (int k = 0; k < USMEM / 4; k++) {
            const ulonglong2 u = us2[k];
            const ulonglong2 h = hp2[UREG / 4 + k];
            a2 = ffma2(u.x, h.x, a2);
            a3 = ffma2(u.y, h.y, a3);
        }

        const u64t s = addx2(addx2(a0, a1), addx2(a2, a3));
        const float d = f2lo(s) + f2hi(s);
        const float v = tanh_fast(d + cxw);
        hbuf[wb][tid] = v;

        __syncthreads();
        cxw = nxw;
    }

    // final h in hbuf[0] (t=511 wrote wb=0). Head: 32 threads -> hidden, 1 -> softmax.
    if (tid < 32) {
        float acc = b1v[tid];
        const float* hr = hbuf[0];
        #pragma unroll 8
        for (int j = 0; j < 256; j++)
            acc = fmaf(hr[j], __ldg(W1 + j * 32 + tid), acc);
        hid[tid] = fmaxf(acc, 0.0f);
    }
    __syncthreads();
    if (tid == 0) {
        float l0 = b2v[0], l1 = b2v[1];
        #pragma unroll
        for (int k = 0; k < 32; k++) {
            const float hv = hid[k];
            l0 = fmaf(hv, __ldg(W2 + k * 2 + 0), l0);
            l1 = fmaf(hv, __ldg(W2 + k * 2 + 1), l1);
        }
        const float m = fmaxf(l0, l1);
        const float e0 = expf(l0 - m);
        const float e1 = expf(l1 - m);
        const float inv = 1.0f / (e0 + e1);
        outp[b * 2 + 0] = e0 * inv;
        outp[b * 2 + 1] = e1 * inv;
    }
}

// ---------------------------------------------------------------------------
extern "C" void kernel_launch(void* const* d_in, const int* in_sizes, int n_in,
                              void* d_out, int out_size)
{
    const int*   sent = (const int*)d_in[0];
    const float* emb  = (const float*)d_in[1];
    const float* Wm   = (const float*)d_in[2];
    const float* Um   = (const float*)d_in[3];
    const float* W1   = (const float*)d_in[4];
    const float* b1v  = (const float*)d_in[5];
    const float* W2   = (const float*)d_in[6];
    const float* b2v  = (const float*)d_in[7];
    float* outp = (float*)d_out;
    (void)in_sizes; (void)n_in; (void)out_size;

    const int usm_bytes = 256 * USTRIDE * (int)sizeof(float);   // 86016
    cudaFuncSetAttribute(rnn_kernel, cudaFuncAttributeMaxDynamicSharedMemorySize,
                         usm_bytes);

    xw_kernel<<<1024, 256>>>(sent, emb, Wm);
    rnn_kernel<<<B_, 256, usm_bytes>>>(Um, W1, b1v, W2, b2v, outp);
}